// round 1
// baseline (speedup 1.0000x reference)
#include <cuda_runtime.h>
#include <math.h>

// CNO_LReLu: per-row (B*C = 8192 rows):
//   y = bicubic_antialias_upsample_x2(x)   (2048 -> 4096)
//   y = leaky_relu(y, 0.01)
//   out = bicubic_antialias_downsample_x2(y) (4096 -> 2048)
//
// Interior weights are fully periodic; hardcoded exact stencils.
// Edge outputs (few per row) use the generic drop-OOB + renormalize path.

#define IN_N   2048
#define MID_N  4096
#define OUT_N  2048
#define N_ROWS 8192

__device__ __forceinline__ float keys_cubic(float x) {
    // Keys cubic, a = -0.5
    float ax = fabsf(x);
    if (ax <= 1.0f) return (1.5f * ax - 2.5f) * ax * ax + 1.0f;
    if (ax < 2.0f)  return -0.5f * (((ax - 5.0f) * ax + 8.0f) * ax - 4.0f);
    return 0.0f;
}

// Generic upsample output m (fscale = 1, 5 taps), with OOB drop + renorm.
__device__ __forceinline__ float generic_up(const float* sx, int m) {
    float center = (m + 0.5f) * 0.5f;
    int xmin = (int)floorf(center - 1.5f);
    float sum = 0.0f, acc = 0.0f;
#pragma unroll
    for (int t = 0; t < 5; t++) {
        int idx = xmin + t;
        float w = keys_cubic((float)idx + 0.5f - center);
        if (idx >= 0 && idx < IN_N) {
            sum += w;
            acc = fmaf(w, sx[idx], acc);
        }
    }
    return acc / sum;
}

// Generic downsample output o (fscale = 2, 9 taps), with OOB drop + renorm.
__device__ __forceinline__ float generic_down(const float* syE, const float* syO, int o) {
    float center = (o + 0.5f) * 2.0f;
    int xmin = (int)floorf(center - 3.5f);
    float sum = 0.0f, acc = 0.0f;
#pragma unroll
    for (int t = 0; t < 9; t++) {
        int idx = xmin + t;
        float w = keys_cubic(((float)idx + 0.5f - center) * 0.5f);
        if (idx >= 0 && idx < MID_N) {
            sum += w;
            float yv = (idx & 1) ? syO[idx >> 1] : syE[idx >> 1];
            acc = fmaf(w, yv, acc);
        }
    }
    return acc / sum;
}

__global__ __launch_bounds__(256) void cno_lrelu_kernel(
    const float* __restrict__ x, float* __restrict__ out)
{
    __shared__ float sx[IN_N];     // input row
    __shared__ float syE[OUT_N];   // y[2k]   (post-leaky)
    __shared__ float syO[OUT_N];   // y[2k+1] (post-leaky)

    const int row = blockIdx.x;
    const int tid = threadIdx.x;
    const float* __restrict__ xr = x + (size_t)row * IN_N;
    float* __restrict__ orow = out + (size_t)row * OUT_N;

    // ---- Phase 1: load x row into smem (vectorized, coalesced) ----
    {
        const float4* __restrict__ xv = reinterpret_cast<const float4*>(xr);
        float4* sxv = reinterpret_cast<float4*>(sx);
#pragma unroll
        for (int j = 0; j < 2; j++) {
            sxv[tid + 256 * j] = xv[tid + 256 * j];
        }
    }
    __syncthreads();

    // ---- Phase 2: upsample x2 + LeakyReLU, write even/odd y planes ----
    // y[2k]   taps x[k-2..k+1], w = {-6, 58, 222, -18}/256
    // y[2k+1] taps x[k-1..k+2], w = {-18, 222, 58, -6}/256
#pragma unroll
    for (int j = 0; j < 8; j++) {
        int k = tid + 256 * j;  // lane-stride-1 across warp -> conflict-free LDS/STS
        float yE, yO;
        if (k >= 2 && k <= IN_N - 3) {
            float a = sx[k - 2], b = sx[k - 1], c = sx[k];
            float d = sx[k + 1], e = sx[k + 2];
            yE = fmaf(-0.0234375f, a,
                 fmaf( 0.2265625f, b,
                 fmaf( 0.8671875f, c, -0.0703125f * d)));
            yO = fmaf(-0.0703125f, b,
                 fmaf( 0.8671875f, c,
                 fmaf( 0.2265625f, d, -0.0234375f * e)));
        } else {
            yE = generic_up(sx, 2 * k);
            yO = generic_up(sx, 2 * k + 1);
        }
        yE = (yE >= 0.0f) ? yE : 0.01f * yE;
        yO = (yO >= 0.0f) ? yO : 0.01f * yO;
        syE[k] = yE;
        syO[k] = yO;
    }
    __syncthreads();

    // ---- Phase 3: downsample x2 (symmetric 8-tap stencil) ----
    // out[o] = sum_t DW[t] * y[2o-3+t], DW = {-3,-9,29,111,111,29,-9,-3}/256
#pragma unroll
    for (int j = 0; j < 8; j++) {
        int o = tid + 256 * j;  // lane-stride-1 -> conflict-free
        float r;
        if (o >= 2 && o <= OUT_N - 3) {
            r = fmaf(-0.01171875f, (syO[o - 2] + syE[o + 2]),
                fmaf(-0.03515625f, (syE[o - 1] + syO[o + 1]),
                fmaf( 0.11328125f, (syO[o - 1] + syE[o + 1]),
                      0.43359375f * (syE[o] + syO[o]))));
        } else {
            r = generic_down(syE, syO, o);
        }
        orow[o] = r;
    }
}

extern "C" void kernel_launch(void* const* d_in, const int* in_sizes, int n_in,
                              void* d_out, int out_size) {
    const float* x = (const float*)d_in[0];
    float* out = (float*)d_out;
    (void)in_sizes; (void)n_in; (void)out_size;
    cno_lrelu_kernel<<<N_ROWS, 256>>>(x, out);
}